// round 3
// baseline (speedup 1.0000x reference)
#include <cuda_runtime.h>
#include <cuda_fp16.h>
#include <cstdint>
#include <cmath>

// ---------------- problem dims ----------------
#define BATCHSZ   4096
#define UNITS     2048
#define KDIM      2048          // per-source K
#define KTOT      6144          // 3 * KDIM
#define NTOT      8192          // 4 * UNITS

// ---------------- GEMM tile config ------------
#define MT        128           // CTA M tile
#define NT        256           // CTA N tile
#define KT        64            // K chunk per stage (halfs)
#define NSTAGE    4
#define NKT       (KTOT / KT)   // 96

#define A_STAGE_B (MT * KT * 2)              // 16384 (128 rows x 128B)
#define B_STAGE_B (KT * NT * 2)              // 32768 (64 rows x 512B)
#define STAGE_B   (A_STAGE_B + B_STAGE_B)    // 49152
#define SMEM_TOTAL (NSTAGE * STAGE_B)        // 196608

#define WSCALE    1024.0f
#define INV_WSCALE (1.0f / 1024.0f)

#define ASEG ((size_t)BATCHSZ * KDIM)        // 8388608
#define WSEG ((size_t)KDIM * NTOT)           // 16777216

// ---------------- device scratch --------------
__device__ __half g_Ah[(size_t)3 * BATCHSZ * KDIM];   // fp16 activations (3 segs)
__device__ __half g_Wh[(size_t)KTOT * NTOT];          // fp16 weights (x1024), [kglob][n]
__device__ float  g_X[(size_t)BATCHSZ * NTOT];        // pre-activation x (x1024)

// ---------------- asm helpers -----------------
__device__ __forceinline__ void cp_async16(uint32_t dst, const void* src) {
    asm volatile("cp.async.cg.shared.global [%0], [%1], 16;"
                 :: "r"(dst), "l"(__cvta_generic_to_global(src)) : "memory");
}
__device__ __forceinline__ void cp_commit() {
    asm volatile("cp.async.commit_group;" ::: "memory");
}
__device__ __forceinline__ void cp_wait2() {
    asm volatile("cp.async.wait_group 2;" ::: "memory");
}
__device__ __forceinline__ void ldsm_x4(uint32_t* r, uint32_t addr) {
    asm volatile("ldmatrix.sync.aligned.m8n8.x4.shared.b16 {%0,%1,%2,%3}, [%4];"
                 : "=r"(r[0]), "=r"(r[1]), "=r"(r[2]), "=r"(r[3]) : "r"(addr));
}
__device__ __forceinline__ void ldsm_x4_t(uint32_t* r, uint32_t addr) {
    asm volatile("ldmatrix.sync.aligned.m8n8.x4.trans.shared.b16 {%0,%1,%2,%3}, [%4];"
                 : "=r"(r[0]), "=r"(r[1]), "=r"(r[2]), "=r"(r[3]) : "r"(addr));
}
__device__ __forceinline__ void mma16816(float* c, const uint32_t* a, uint32_t b0, uint32_t b1) {
    asm volatile("mma.sync.aligned.m16n8k16.row.col.f32.f16.f16.f32 "
                 "{%0,%1,%2,%3}, {%4,%5,%6,%7}, {%8,%9}, {%0,%1,%2,%3};"
                 : "+f"(c[0]), "+f"(c[1]), "+f"(c[2]), "+f"(c[3])
                 : "r"(a[0]), "r"(a[1]), "r"(a[2]), "r"(a[3]), "r"(b0), "r"(b1));
}

// ---------------- kernel 0: fp32 -> fp16 convert into device scratch ---------
// which = 0: dst = g_Ah + seg*ASEG, scale 1.0
// which = 1: dst = g_Wh + seg*WSEG, scale WSCALE
__global__ void __launch_bounds__(256) conv_kernel(const float* __restrict__ src,
                                                   int which, int seg)
{
    size_t i = ((size_t)blockIdx.x * 256 + threadIdx.x) * 4;
    __half* dst = which ? (g_Wh + (size_t)seg * WSEG) : (g_Ah + (size_t)seg * ASEG);
    float scale = which ? WSCALE : 1.0f;
    float4 v = *(const float4*)(src + i);
    __half2 h0 = __floats2half2_rn(v.x * scale, v.y * scale);
    __half2 h1 = __floats2half2_rn(v.z * scale, v.w * scale);
    *(__half2*)(dst + i)     = h0;
    *(__half2*)(dst + i + 2) = h1;
}

// ---------------- kernel 1: pipelined fp16 GEMM (mma.sync) -------------------
// x[M, 8192] = sum over 3 segs of A_seg[M, 2048] @ W_seg[2048, 8192]
__global__ void __launch_bounds__(256) gemm_kernel()
{
    extern __shared__ char smem[];
    uint32_t sb = (uint32_t)__cvta_generic_to_shared(smem);
    const int tid  = threadIdx.x;
    const int lane = tid & 31;
    const int wid  = tid >> 5;
    const int m0 = blockIdx.y * MT;
    const int n0 = blockIdx.x * NT;
    const int wm = (wid >> 2) * 64;   // warp M offset within CTA tile
    const int wn = (wid & 3) * 64;    // warp N offset within CTA tile

    // ---- stage loader (cp.async, xor swizzle) ----
    auto load_stage = [&](int slot, int kt) {
        int kg   = kt * KT;
        int seg  = kg >> 11;
        int koff = kg & (KDIM - 1);
        const __half* Asrc = g_Ah + (size_t)seg * ASEG
                                  + (size_t)m0 * KDIM + koff;
        const __half* Bsrc = g_Wh + (size_t)kg * NTOT + n0;
        uint32_t As = sb + slot * STAGE_B;
        uint32_t Bs = As + A_STAGE_B;
#pragma unroll
        for (int u = tid; u < 3072; u += 256) {
            if (u < 1024) {                        // A: 128 rows x 8 chunks(16B)
                int r = u >> 3, c8 = u & 7;
                uint32_t dst = As + r * 128 + ((c8 ^ (r & 7)) << 4);
                cp_async16(dst, Asrc + (size_t)r * KDIM + c8 * 8);
            } else {                               // B: 64 rows x 32 chunks(16B)
                int v = u - 1024;
                int k = v >> 5, c32 = v & 31;
                uint32_t sw = (uint32_t)((c32 & 24) | ((c32 & 7) ^ (k & 7)));
                uint32_t dst = Bs + k * 512 + (sw << 4);
                cp_async16(dst, Bsrc + (size_t)k * NTOT + c32 * 8);
            }
        }
    };

    float acc[4][8][4];
#pragma unroll
    for (int mi = 0; mi < 4; mi++)
#pragma unroll
        for (int nj = 0; nj < 8; nj++)
#pragma unroll
            for (int q = 0; q < 4; q++) acc[mi][nj][q] = 0.0f;

    // prologue: fill 3 stages
    for (int s = 0; s < NSTAGE - 1; s++) { load_stage(s, s); cp_commit(); }

    for (int kt = 0; kt < NKT; kt++) {
        cp_wait2();              // stage kt resident (<=2 younger groups pending)
        __syncthreads();         // publish copies; all warps done with stage kt-1
        if (kt + NSTAGE - 1 < NKT) load_stage((kt + NSTAGE - 1) & (NSTAGE - 1), kt + NSTAGE - 1);
        cp_commit();             // commit every iter (possibly empty) to keep count uniform

        uint32_t As = sb + (kt & (NSTAGE - 1)) * STAGE_B;
        uint32_t Bs = As + A_STAGE_B;
#pragma unroll
        for (int kk = 0; kk < 4; kk++) {
            uint32_t a[4][4], b[4][4];
#pragma unroll
            for (int mi = 0; mi < 4; mi++) {
                int r = wm + mi * 16 + (lane & 15);
                uint32_t addr = As + r * 128 + ((((2 * kk) + (lane >> 4)) ^ (r & 7)) << 4);
                ldsm_x4(a[mi], addr);
            }
#pragma unroll
            for (int nf = 0; nf < 4; nf++) {
                int k = kk * 16 + (lane & 15);
                int c32 = (wn >> 3) + nf * 2 + (lane >> 4);
                uint32_t sw = (uint32_t)((c32 & 24) | ((c32 & 7) ^ (lane & 7)));
                uint32_t addr = Bs + k * 512 + (sw << 4);
                ldsm_x4_t(b[nf], addr);
            }
#pragma unroll
            for (int mi = 0; mi < 4; mi++)
#pragma unroll
                for (int nj = 0; nj < 8; nj++)
                    mma16816(acc[mi][nj], a[mi], b[nj >> 1][(nj & 1) * 2],
                                                  b[nj >> 1][(nj & 1) * 2 + 1]);
        }
    }

    // ---- write x tile ----
    float* Xp = g_X + (size_t)m0 * NTOT + n0;
#pragma unroll
    for (int mi = 0; mi < 4; mi++) {
        int mrow = wm + mi * 16 + (lane >> 2);
#pragma unroll
        for (int nj = 0; nj < 8; nj++) {
            int ncol = wn + nj * 8 + 2 * (lane & 3);
            float2 v0 = make_float2(acc[mi][nj][0], acc[mi][nj][1]);
            float2 v1 = make_float2(acc[mi][nj][2], acc[mi][nj][3]);
            *(float2*)(Xp + (size_t)mrow * NTOT + ncol)       = v0;
            *(float2*)(Xp + (size_t)(mrow + 8) * NTOT + ncol) = v1;
        }
    }
}

// ---------------- kernel 2: fused LSTM epilogue ------------------------------
__global__ void __launch_bounds__(256) lstm_kernel(const float* __restrict__ c_tm1,
                                                   const float* __restrict__ bias,
                                                   float* __restrict__ out)
{
    size_t i = ((size_t)blockIdx.x * 256 + threadIdx.x) * 4;   // over 4096*2048
    int m = (int)(i >> 11);
    int u = (int)(i & (UNITS - 1));
    const float* xr = g_X + (size_t)m * NTOT;

    float4 xi = *(const float4*)(xr + u);
    float4 xf = *(const float4*)(xr + u + UNITS);
    float4 xc = *(const float4*)(xr + u + 2 * UNITS);
    float4 xo = *(const float4*)(xr + u + 3 * UNITS);
    float4 bi = *(const float4*)(bias + u);
    float4 bf = *(const float4*)(bias + u + UNITS);
    float4 bc = *(const float4*)(bias + u + 2 * UNITS);
    float4 bo = *(const float4*)(bias + u + 3 * UNITS);
    float4 cp = *(const float4*)(c_tm1 + i);

    const float S = INV_WSCALE;
    float vxi[4] = {xi.x, xi.y, xi.z, xi.w};
    float vxf[4] = {xf.x, xf.y, xf.z, xf.w};
    float vxc[4] = {xc.x, xc.y, xc.z, xc.w};
    float vxo[4] = {xo.x, xo.y, xo.z, xo.w};
    float vbi[4] = {bi.x, bi.y, bi.z, bi.w};
    float vbf[4] = {bf.x, bf.y, bf.z, bf.w};
    float vbc[4] = {bc.x, bc.y, bc.z, bc.w};
    float vbo[4] = {bo.x, bo.y, bo.z, bo.w};
    float vc[4]  = {cp.x, cp.y, cp.z, cp.w};
    float vh[4];
#pragma unroll
    for (int q = 0; q < 4; q++) {
        float zi = fmaf(vxi[q], S, vbi[q]);
        float zf = fmaf(vxf[q], S, vbf[q]);
        float zc = fmaf(vxc[q], S, vbc[q]);
        float zo = fmaf(vxo[q], S, vbo[q]);
        float gi = __saturatef(fmaf(0.2f, zi, 0.5f));
        float gf = __saturatef(fmaf(0.2f, zf, 0.5f));
        float go = __saturatef(fmaf(0.2f, zo, 0.5f));
        float cnew = gf * vc[q] + gi * tanhf(zc);
        vh[q] = go * tanhf(cnew);
    }
    *(float4*)(out + i) = make_float4(vh[0], vh[1], vh[2], vh[3]);
}

// ---------------- launch -----------------------------------------------------
extern "C" void kernel_launch(void* const* d_in, const int* in_sizes, int n_in,
                              void* d_out, int out_size)
{
    const float* inputs = (const float*)d_in[0];
    const float* h_tm1  = (const float*)d_in[1];
    const float* c_tm1  = (const float*)d_in[2];
    const float* z_tm1  = (const float*)d_in[3];
    const float* kern   = (const float*)d_in[4];
    const float* rkern  = (const float*)d_in[5];
    const float* rlat   = (const float*)d_in[6];
    const float* bias   = (const float*)d_in[7];
    float* out = (float*)d_out;

    // Unconditional (no static guards). Idempotent; attribute persists from the
    // pre-capture correctness call even if a capture-time call is a no-op.
    (void)cudaFuncSetAttribute(gemm_kernel,
                               cudaFuncAttributeMaxDynamicSharedMemorySize, SMEM_TOTAL);

    // activations -> fp16 (scratch addressed inside kernel via selector)
    conv_kernel<<<(unsigned)(ASEG / 1024), 256>>>(inputs, 0, 0);
    conv_kernel<<<(unsigned)(ASEG / 1024), 256>>>(h_tm1,  0, 1);
    conv_kernel<<<(unsigned)(ASEG / 1024), 256>>>(z_tm1,  0, 2);
    // weights -> fp16 * 1024
    conv_kernel<<<(unsigned)(WSEG / 1024), 256>>>(kern,  1, 0);
    conv_kernel<<<(unsigned)(WSEG / 1024), 256>>>(rkern, 1, 1);
    conv_kernel<<<(unsigned)(WSEG / 1024), 256>>>(rlat,  1, 2);

    gemm_kernel<<<dim3(NTOT / NT, BATCHSZ / MT), 256, SMEM_TOTAL>>>();

    lstm_kernel<<<(unsigned)((size_t)BATCHSZ * UNITS / 1024), 256>>>(c_tm1, bias, out);
}